// round 14
// baseline (speedup 1.0000x reference)
#include <cuda_runtime.h>
#include <cuda_bf16.h>
#include <cstdint>

#define NN 50000
#define NE 800000
#define MAXF 512

// ---------------------------------------------------------------------------
// Scratch (__device__ globals per harness allocation rules)
// ---------------------------------------------------------------------------
__device__ float g_x[NN * MAXF];
__device__ float g_t[NN * MAXF];
__device__ __nv_bfloat16 g_xh[NN * MAXF], g_xl[NN * MAXF];
__device__ __nv_bfloat16 g_th[NN * MAXF], g_tl[NN * MAXF];
__device__ float g_dinv[NN];
__device__ int   g_cnt[NN];
__device__ int   g_rowptr[NN + 1];
__device__ int   g_cursor[NN];
__device__ int   g_esrc[NE];
__device__ float g_enorm[NE];
__device__ int   g_bsum[64];
__device__ __nv_bfloat16 g_w2h[256 * 64],  g_w2l[256 * 64];
__device__ __nv_bfloat16 g_w3h[512 * 256], g_w3l[512 * 256];
__device__ __nv_bfloat16 g_w4h[256 * 512], g_w4l[256 * 512];
__device__ __nv_bfloat16 g_w5h[64 * 256],  g_w5l[64 * 256];

// ---------------------------------------------------------------------------
// helpers
// ---------------------------------------------------------------------------
__device__ __forceinline__ uint32_t smem_u32(const void* p) {
    uint32_t a;
    asm("{ .reg .u64 t; cvta.to.shared.u64 t, %1; cvt.u32.u64 %0, t; }" : "=r"(a) : "l"(p));
    return a;
}
__device__ __forceinline__ void cp16(uint32_t dst, const void* src) {
    asm volatile("cp.async.cg.shared.global [%0], [%1], 16;" :: "r"(dst), "l"(src) : "memory");
}
#define CP_COMMIT() asm volatile("cp.async.commit_group;" ::: "memory")

#define LDSM4(r0, r1, r2, r3, addr) \
    asm volatile("ldmatrix.sync.aligned.m8n8.x4.shared.b16 {%0,%1,%2,%3}, [%4];" \
                 : "=r"(r0), "=r"(r1), "=r"(r2), "=r"(r3) : "r"(addr))

__device__ __forceinline__ void mma_bf16(float* d, const uint32_t* a, uint32_t b0, uint32_t b1) {
    asm volatile("mma.sync.aligned.m16n8k16.row.col.f32.bf16.bf16.f32 "
                 "{%0,%1,%2,%3}, {%4,%5,%6,%7}, {%8,%9}, {%0,%1,%2,%3};"
                 : "+f"(d[0]), "+f"(d[1]), "+f"(d[2]), "+f"(d[3])
                 : "r"(a[0]), "r"(a[1]), "r"(a[2]), "r"(a[3]), "r"(b0), "r"(b1));
}

__device__ __forceinline__ void split_bf16(float v, __nv_bfloat16& h, __nv_bfloat16& l) {
    h = __float2bfloat16(v);
    l = __float2bfloat16(v - __bfloat162float(h));
}

// ---------------------------------------------------------------------------
// CSR build: count -> scan1 (fused dinv) -> scan23 -> fill
// ---------------------------------------------------------------------------
__global__ void cnt_acc_kernel(const int* __restrict__ dst, int* cnt) {
    int e = blockIdx.x * blockDim.x + threadIdx.x;
    if (e < NE) atomicAdd(&cnt[dst[e]], 1);
}
#define SCAN_BLOCKS ((NN + 1023) / 1024)
__global__ __launch_bounds__(1024) void scan1_kernel(const int* __restrict__ cnt,
                                                     int* rowptr, int* bsum, float* dinv) {
    __shared__ int s[1024];
    int i = blockIdx.x * 1024 + threadIdx.x;
    int v = (i < NN) ? cnt[i] : 0;
    if (i < NN) dinv[i] = rsqrtf((float)(v + 1));
    s[threadIdx.x] = v;
    __syncthreads();
    for (int off = 1; off < 1024; off <<= 1) {
        int t = (threadIdx.x >= off) ? s[threadIdx.x - off] : 0;
        __syncthreads();
        if (threadIdx.x >= off) s[threadIdx.x] += t;
        __syncthreads();
    }
    if (i < NN) rowptr[i] = s[threadIdx.x] - v;
    if (threadIdx.x == 1023) bsum[blockIdx.x] = s[1023];
}
__global__ __launch_bounds__(1024) void scan23_kernel(int* rowptr, const int* __restrict__ bsum,
                                                      int* cursor) {
    __shared__ int spre;
    if (threadIdx.x == 0) {
        int run = 0;
        for (int b = 0; b < blockIdx.x; b++) run += bsum[b];
        spre = run;
        if (blockIdx.x == SCAN_BLOCKS - 1)
            rowptr[NN] = run + bsum[SCAN_BLOCKS - 1];
    }
    __syncthreads();
    int pre = spre;
    int i = blockIdx.x * 1024 + threadIdx.x;
    if (i < NN) { int r = rowptr[i] + pre; rowptr[i] = r; cursor[i] = r; }
}
__global__ void fill_kernel(const int* __restrict__ src, const int* __restrict__ dst,
                            const float* __restrict__ dinv,
                            int* cursor, int* esrc, float* enorm) {
    int e = blockIdx.x * blockDim.x + threadIdx.x;
    if (e >= NE) return;
    int s = src[e], d = dst[e];
    int pos = atomicAdd(&cursor[d], 1);
    esrc[pos] = s;
    enorm[pos] = dinv[s] * dinv[d];
}

// ---------------------------------------------------------------------------
// Merged weight transpose + bf16 hi/lo split (all 4 weights, one launch)
// ---------------------------------------------------------------------------
__global__ void wsplit_all_kernel(const float* __restrict__ W2, const float* __restrict__ W3,
                                  const float* __restrict__ W4, const float* __restrict__ W5,
                                  __nv_bfloat16* o2h, __nv_bfloat16* o2l,
                                  __nv_bfloat16* o3h, __nv_bfloat16* o3l,
                                  __nv_bfloat16* o4h, __nv_bfloat16* o4l,
                                  __nv_bfloat16* o5h, __nv_bfloat16* o5l) {
    int bid = blockIdx.x;
    const float* W; __nv_bfloat16 *Th, *Tl;
    int K, F, t, fx;
    if (bid < 16)       { W = W2; Th = o2h; Tl = o2l; K = 64;  F = 256; t = bid;       fx = 8;  }
    else if (bid < 144) { W = W3; Th = o3h; Tl = o3l; K = 256; F = 512; t = bid - 16;  fx = 16; }
    else if (bid < 272) { W = W4; Th = o4h; Tl = o4l; K = 512; F = 256; t = bid - 144; fx = 8;  }
    else                { W = W5; Th = o5h; Tl = o5l; K = 256; F = 64;  t = bid - 272; fx = 2;  }
    int f0 = (t % fx) * 32, k0 = (t / fx) * 32;

    __shared__ float tile[32][33];
    for (int i = threadIdx.y; i < 32; i += 8) {
        int k = k0 + i, f = f0 + threadIdx.x;
        tile[i][threadIdx.x] = W[(long)k * F + f];
    }
    __syncthreads();
    for (int i = threadIdx.y; i < 32; i += 8) {
        int f = f0 + i, k = k0 + threadIdx.x;
        __nv_bfloat16 h, l;
        split_bf16(tile[threadIdx.x][i], h, l);
        Th[(long)f * K + k] = h;
        Tl[(long)f * K + k] = l;
    }
}

// ---------------------------------------------------------------------------
// Vectorized gather F=256: 1 warp per node, 2 float4 per lane.
// ---------------------------------------------------------------------------
template <bool BIAS, bool RELU, int OUT>
__global__ __launch_bounds__(256) void gather256_kernel(
    const int* __restrict__ rowptr, const int* __restrict__ esrc,
    const float* __restrict__ enorm, const float* __restrict__ in,
    const float* __restrict__ dinv, const float* __restrict__ bias,
    float* __restrict__ out, __nv_bfloat16* __restrict__ oh, __nv_bfloat16* __restrict__ ol)
{
    int gw = (blockIdx.x * blockDim.x + threadIdx.x) >> 5;
    int lane = threadIdx.x & 31;
    if (gw >= NN) return;

    float di = dinv[gw];
    float selfw = di * di;
    const float4* self = (const float4*)(in + (long)gw * 256);
    float4 a0 = self[lane], a1 = self[32 + lane];
    float4 acc0 = make_float4(a0.x * selfw, a0.y * selfw, a0.z * selfw, a0.w * selfw);
    float4 acc1 = make_float4(a1.x * selfw, a1.y * selfw, a1.z * selfw, a1.w * selfw);

    int e0 = rowptr[gw], e1 = rowptr[gw + 1];
    for (int e = e0; e < e1; e++) {
        int s = esrc[e];
        float nv = enorm[e];
        const float4* r = (const float4*)(in + (long)s * 256);
        float4 h0 = r[lane], h1 = r[32 + lane];
        acc0.x += h0.x * nv; acc0.y += h0.y * nv; acc0.z += h0.z * nv; acc0.w += h0.w * nv;
        acc1.x += h1.x * nv; acc1.y += h1.y * nv; acc1.z += h1.z * nv; acc1.w += h1.w * nv;
    }

    if (BIAS) {
        float4 b0 = ((const float4*)bias)[lane], b1 = ((const float4*)bias)[32 + lane];
        acc0.x += b0.x; acc0.y += b0.y; acc0.z += b0.z; acc0.w += b0.w;
        acc1.x += b1.x; acc1.y += b1.y; acc1.z += b1.z; acc1.w += b1.w;
    }
    if (RELU) {
        acc0.x = fmaxf(acc0.x, 0.f); acc0.y = fmaxf(acc0.y, 0.f);
        acc0.z = fmaxf(acc0.z, 0.f); acc0.w = fmaxf(acc0.w, 0.f);
        acc1.x = fmaxf(acc1.x, 0.f); acc1.y = fmaxf(acc1.y, 0.f);
        acc1.z = fmaxf(acc1.z, 0.f); acc1.w = fmaxf(acc1.w, 0.f);
    }
    if (OUT == 0) {
        float4* o = (float4*)(out + (long)gw * 256);
        o[lane] = acc0; o[32 + lane] = acc1;
    } else {
        float v[8] = {acc0.x, acc0.y, acc0.z, acc0.w, acc1.x, acc1.y, acc1.z, acc1.w};
        #pragma unroll
        for (int q = 0; q < 2; q++) {
            long base = (long)gw * 256 + (q ? 128 : 0) + lane * 4;
            __nv_bfloat16 h0, l0, h1, l1, h2, l2, h3, l3;
            split_bf16(v[q * 4 + 0], h0, l0); split_bf16(v[q * 4 + 1], h1, l1);
            split_bf16(v[q * 4 + 2], h2, l2); split_bf16(v[q * 4 + 3], h3, l3);
            *(__nv_bfloat162*)(oh + base)     = __nv_bfloat162(h0, h1);
            *(__nv_bfloat162*)(oh + base + 2) = __nv_bfloat162(h2, h3);
            *(__nv_bfloat162*)(ol + base)     = __nv_bfloat162(l0, l1);
            *(__nv_bfloat162*)(ol + base + 2) = __nv_bfloat162(l2, l3);
        }
    }
}

// ---------------------------------------------------------------------------
// Vectorized gather F=64: 1 warp per node, float2 per lane.
// ---------------------------------------------------------------------------
template <bool BIAS, bool RELU, int OUT>
__global__ __launch_bounds__(256) void gather64_kernel(
    const int* __restrict__ rowptr, const int* __restrict__ esrc,
    const float* __restrict__ enorm, const float* __restrict__ in,
    const float* __restrict__ dinv, const float* __restrict__ bias,
    float* __restrict__ out, __nv_bfloat16* __restrict__ oh, __nv_bfloat16* __restrict__ ol)
{
    int gw = (blockIdx.x * blockDim.x + threadIdx.x) >> 5;
    int lane = threadIdx.x & 31;
    if (gw >= NN) return;

    float di = dinv[gw];
    float selfw = di * di;
    float2 a = ((const float2*)(in + (long)gw * 64))[lane];
    float2 acc = make_float2(a.x * selfw, a.y * selfw);

    int e0 = rowptr[gw], e1 = rowptr[gw + 1];
    for (int e = e0; e < e1; e++) {
        int s = esrc[e];
        float nv = enorm[e];
        float2 h = ((const float2*)(in + (long)s * 64))[lane];
        acc.x += h.x * nv; acc.y += h.y * nv;
    }

    if (BIAS) {
        float2 bb = ((const float2*)bias)[lane];
        acc.x += bb.x; acc.y += bb.y;
    }
    if (RELU) { acc.x = fmaxf(acc.x, 0.f); acc.y = fmaxf(acc.y, 0.f); }
    if (OUT == 0) {
        ((float2*)(out + (long)gw * 64))[lane] = acc;
    } else {
        __nv_bfloat16 h0, l0, h1, l1;
        split_bf16(acc.x, h0, l0); split_bf16(acc.y, h1, l1);
        *(__nv_bfloat162*)(oh + (long)gw * 64 + lane * 2) = __nv_bfloat162(h0, h1);
        *(__nv_bfloat162*)(ol + (long)gw * 64 + lane * 2) = __nv_bfloat162(l0, l1);
    }
}

// ---------------------------------------------------------------------------
// Generic scalar gather (F=35, F=16)
// ---------------------------------------------------------------------------
template <int F, bool BIAS, bool RELU>
__global__ __launch_bounds__(256) void gather_kernel(
    const int* __restrict__ rowptr, const int* __restrict__ esrc,
    const float* __restrict__ enorm, const float* __restrict__ in,
    const float* __restrict__ dinv, const float* __restrict__ bias,
    float* __restrict__ out)
{
    int gw = (blockIdx.x * blockDim.x + threadIdx.x) >> 5;
    int lane = threadIdx.x & 31;
    if (gw >= NN) return;
    constexpr int FPL = (F + 31) / 32;

    float acc[FPL];
    float di = dinv[gw];
    float selfw = di * di;
    const float* hd = &in[(long)gw * F];
    #pragma unroll
    for (int i = 0; i < FPL; i++) {
        int f = lane + 32 * i;
        acc[i] = (f < F) ? hd[f] * selfw : 0.0f;
    }
    int e0 = rowptr[gw], e1 = rowptr[gw + 1];
    for (int e = e0; e < e1; e++) {
        int s = esrc[e];
        float nv = enorm[e];
        const float* hs = &in[(long)s * F];
        #pragma unroll
        for (int i = 0; i < FPL; i++) {
            int f = lane + 32 * i;
            if (f < F) acc[i] += hs[f] * nv;
        }
    }
    float* o = &out[(long)gw * F];
    #pragma unroll
    for (int i = 0; i < FPL; i++) {
        int f = lane + 32 * i;
        if (f < F) {
            float v = acc[i];
            if (BIAS) v += bias[f];
            if (RELU) v = fmaxf(v, 0.0f);
            o[f] = v;
        }
    }
}

// ---------------------------------------------------------------------------
// SW128 swizzle
// ---------------------------------------------------------------------------
#define SWZ(row, byteoff) (((row) * 128 + (byteoff)) ^ (((row) & 7) << 4))

// ---------------------------------------------------------------------------
// hmma256: CTA tile 128x256, warp tile 64x64 (WARPS_M=2 x WARPS_N=4),
// 2-stage cp.async, SW128. D += Ah*Bh + Al*Bh + Ah*Bl.
// MODE: 0 = fp32 out, 1 = bias+relu fp32 out, 2 = bias+relu bf16-split out
// ---------------------------------------------------------------------------
template <int MODE>
__global__ __launch_bounds__(256) void hmma256_kernel(
    const __nv_bfloat16* __restrict__ Ah, const __nv_bfloat16* __restrict__ Al,
    const __nv_bfloat16* __restrict__ Bh, const __nv_bfloat16* __restrict__ Bl,
    const float* __restrict__ bias,
    float* __restrict__ Cf, __nv_bfloat16* __restrict__ Ch, __nv_bfloat16* __restrict__ Cl,
    int M, int K, int F)
{
    constexpr int BN = 256;
    constexpr uint32_t A_HI = 0;
    constexpr uint32_t A_LO = 128 * 128;            // 16 KB
    constexpr uint32_t B_HI = 2 * 128 * 128;        // 32 KB
    constexpr uint32_t B_LO = B_HI + BN * 128;      // +32 KB
    constexpr uint32_t STAGE = B_LO + BN * 128;     // 96 KB

    extern __shared__ char smem[];
    uint32_t sb = smem_u32(smem);
    int tid = threadIdx.x;
    int wid = tid >> 5, lane = tid & 31;
    int wm = wid & 1, wn = wid >> 1;                // WARPS_M=2, WARPS_N=4
    int m0 = blockIdx.y * 128, n0 = blockIdx.x * BN;
    int lr = lane & 15, lc = lane >> 4;

    float acc[4][8][4] = {};   // [mi][g*2+h][quad]

    auto load_stage = [&](int kt, int st) {
        uint32_t s0 = sb + st * STAGE;
        long kbase = (long)kt * 64;
        #pragma unroll
        for (int i = 0; i < 4; i++) {
            int idx = tid + i * 256;
            int row = idx >> 3, c = idx & 7;
            int gr = m0 + row; if (gr >= M) gr = M - 1;
            long off = (long)gr * K + kbase + c * 8;
            uint32_t sw = SWZ(row, c * 16);
            cp16(s0 + A_HI + sw, Ah + off);
            cp16(s0 + A_LO + sw, Al + off);
        }
        #pragma unroll
        for (int i = 0; i < 8; i++) {
            int idx = tid + i * 256;
            int row = idx >> 3, c = idx & 7;
            long off = (long)(n0 + row) * K + kbase + c * 8;
            uint32_t sw = SWZ(row, c * 16);
            cp16(s0 + B_HI + sw, Bh + off);
            cp16(s0 + B_LO + sw, Bl + off);
        }
    };

    int nkt = K >> 6;
    load_stage(0, 0); CP_COMMIT();

    for (int kt = 0; kt < nkt; kt++) {
        if (kt + 1 < nkt) {
            load_stage(kt + 1, (kt + 1) & 1);
            CP_COMMIT();
            asm volatile("cp.async.wait_group 1;" ::: "memory");
        } else {
            asm volatile("cp.async.wait_group 0;" ::: "memory");
        }
        __syncthreads();

        uint32_t s0 = sb + (kt & 1) * STAGE;
        #pragma unroll
        for (int k16 = 0; k16 < 4; k16++) {
            int koff = k16 * 32 + lc * 16;
            uint32_t afh[4][4], afl[4][4];
            #pragma unroll
            for (int mi = 0; mi < 4; mi++) {
                int row = wm * 64 + mi * 16 + lr;
                uint32_t sw = SWZ(row, koff);
                LDSM4(afh[mi][0], afh[mi][1], afh[mi][2], afh[mi][3], s0 + A_HI + sw);
                LDSM4(afl[mi][0], afl[mi][1], afl[mi][2], afl[mi][3], s0 + A_LO + sw);
            }
            #pragma unroll
            for (int g = 0; g < 4; g++) {
                int row = wn * 64 + g * 16 + lr;
                uint32_t sw = SWZ(row, koff);
                uint32_t bh[4], bl[4];
                LDSM4(bh[0], bh[1], bh[2], bh[3], s0 + B_HI + sw);
                LDSM4(bl[0], bl[1], bl[2], bl[3], s0 + B_LO + sw);
                #pragma unroll
                for (int mi = 0; mi < 4; mi++) {
                    #pragma unroll
                    for (int h = 0; h < 2; h++) {
                        float* d = acc[mi][g * 2 + h];
                        mma_bf16(d, afh[mi], bh[h], bh[h + 2]);
                        mma_bf16(d, afl[mi], bh[h], bh[h + 2]);
                        mma_bf16(d, afh[mi], bl[h], bl[h + 2]);
                    }
                }
            }
        }
        __syncthreads();
    }

    #pragma unroll
    for (int mi = 0; mi < 4; mi++) {
        #pragma unroll
        for (int j = 0; j < 8; j++) {
            int g = j >> 1, h = j & 1;
            int r0 = m0 + wm * 64 + mi * 16 + (lane >> 2);
            int col = n0 + wn * 64 + g * 16 + h * 8 + (lane & 3) * 2;
            #pragma unroll
            for (int half = 0; half < 2; half++) {
                int r = r0 + half * 8;
                if (r >= M) continue;
                float v0 = acc[mi][j][half * 2 + 0];
                float v1 = acc[mi][j][half * 2 + 1];
                if (MODE >= 1) {
                    v0 = fmaxf(v0 + bias[col], 0.0f);
                    v1 = fmaxf(v1 + bias[col + 1], 0.0f);
                }
                if (MODE <= 1) {
                    *(float2*)(Cf + (long)r * F + col) = make_float2(v0, v1);
                } else {
                    __nv_bfloat16 h0, l0, h1, l1;
                    split_bf16(v0, h0, l0);
                    split_bf16(v1, h1, l1);
                    *(__nv_bfloat162*)(Ch + (long)r * F + col) = __nv_bfloat162(h0, h1);
                    *(__nv_bfloat162*)(Cl + (long)r * F + col) = __nv_bfloat162(l0, l1);
                }
            }
        }
    }
}

// ---------------------------------------------------------------------------
// hmma BN=64 (L5), 3-stage pipeline (unchanged from R13)
// ---------------------------------------------------------------------------
template <int BN, int MODE>
__global__ __launch_bounds__(256) void hmma_gemm_kernel(
    const __nv_bfloat16* __restrict__ Ah, const __nv_bfloat16* __restrict__ Al,
    const __nv_bfloat16* __restrict__ Bh, const __nv_bfloat16* __restrict__ Bl,
    const float* __restrict__ bias,
    float* __restrict__ Cf, __nv_bfloat16* __restrict__ Ch, __nv_bfloat16* __restrict__ Cl,
    int M, int K, int F)
{
    constexpr int WARPS_N = (BN == 128) ? 4 : 2;
    constexpr int WARPS_M = 8 / WARPS_N;
    constexpr int WM = 128 / WARPS_M;
    constexpr int MI = WM / 16;
    constexpr uint32_t A_HI = 0;
    constexpr uint32_t A_LO = 128 * 128;
    constexpr uint32_t B_HI = 2 * 128 * 128;
    constexpr uint32_t B_LO = B_HI + BN * 128;
    constexpr uint32_t STAGE = B_LO + BN * 128;

    extern __shared__ char smem[];
    uint32_t sb = smem_u32(smem);
    int tid = threadIdx.x;
    int wid = tid >> 5, lane = tid & 31;
    int wm = wid % WARPS_M, wn = wid / WARPS_M;
    int m0 = blockIdx.y * 128, n0 = blockIdx.x * BN;
    int lr = lane & 15, lc = lane >> 4;

    float acc[MI][4][4] = {};

    auto load_stage = [&](int kt, int st) {
        uint32_t s0 = sb + st * STAGE;
        long kbase = (long)kt * 64;
        #pragma unroll
        for (int i = 0; i < 4; i++) {
            int idx = tid + i * 256;
            int row = idx >> 3, c = idx & 7;
            int gr = m0 + row; if (gr >= M) gr = M - 1;
            long off = (long)gr * K + kbase + c * 8;
            uint32_t sw = SWZ(row, c * 16);
            cp16(s0 + A_HI + sw, Ah + off);
            cp16(s0 + A_LO + sw, Al + off);
        }
        #pragma unroll
        for (int i = 0; i < BN / 32; i++) {
            int idx = tid + i * 256;
            int row = idx >> 3, c = idx & 7;
            long off = (long)(n0 + row) * K + kbase + c * 8;
            uint32_t sw = SWZ(row, c * 16);
            cp16(s0 + B_HI + sw, Bh + off);
            cp16(s0 + B_LO + sw, Bl + off);
        }
    };

    int nkt = K >> 6;
    load_stage(0, 0); CP_COMMIT();
    if (nkt > 1) { load_stage(1, 1); CP_COMMIT(); }

    for (int kt = 0; kt < nkt; kt++) {
        if (kt + 1 < nkt) {
            asm volatile("cp.async.wait_group 1;" ::: "memory");
        } else {
            asm volatile("cp.async.wait_group 0;" ::: "memory");
        }
        __syncthreads();
        if (kt + 2 < nkt) { load_stage(kt + 2, (kt + 2) % 3); CP_COMMIT(); }

        uint32_t s0 = sb + (kt % 3) * STAGE;
        #pragma unroll
        for (int k16 = 0; k16 < 4; k16++) {
            int koff = k16 * 32 + lc * 16;
            uint32_t afh[MI][4], afl[MI][4];
            #pragma unroll
            for (int mi = 0; mi < MI; mi++) {
                int row = wm * WM + mi * 16 + lr;
                uint32_t sw = SWZ(row, koff);
                LDSM4(afh[mi][0], afh[mi][1], afh[mi][2], afh[mi][3], s0 + A_HI + sw);
                LDSM4(afl[mi][0], afl[mi][1], afl[mi][2], afl[mi][3], s0 + A_LO + sw);
            }
            uint32_t bfh[2][4], bfl[2][4];
            #pragma unroll
            for (int g = 0; g < 2; g++) {
                int row = wn * 32 + g * 16 + lr;
                uint32_t sw = SWZ(row, koff);
                LDSM4(bfh[g][0], bfh[g][1], bfh[g][2], bfh[g][3], s0 + B_HI + sw);
                LDSM4(bfl[g][0], bfl[g][1], bfl[g][2], bfl[g][3], s0 + B_LO + sw);
            }
            #pragma unroll
            for (int mi = 0; mi < MI; mi++) {
                #pragma unroll
                for (int j = 0; j < 4; j++) {
                    int g = j >> 1, h = j & 1;
                    uint32_t b0 = bfh[g][h], b1 = bfh[g][h + 2];
                    mma_bf16(acc[mi][j], afh[mi], b0, b1);
                    mma_bf16(acc[mi][j], afl[mi], b0, b1);
                    mma_bf16(acc[mi][j], afh[mi], bfl[g][h], bfl[g][h + 2]);
                }
            }
        }
        __syncthreads();
    }

    #pragma unroll
    for (int mi = 0; mi < MI; mi++) {
        #pragma unroll
        for (int j = 0; j < 4; j++) {
            int r0 = m0 + wm * WM + mi * 16 + (lane >> 2);
            int col = n0 + wn * 32 + j * 8 + (lane & 3) * 2;
            #pragma unroll
            for (int half = 0; half < 2; half++) {
                int r = r0 + half * 8;
                if (r >= M) continue;
                float v0 = acc[mi][j][half * 2 + 0];
                float v1 = acc[mi][j][half * 2 + 1];
                if (MODE >= 1) {
                    v0 = fmaxf(v0 + bias[col], 0.0f);
                    v1 = fmaxf(v1 + bias[col + 1], 0.0f);
                }
                if (MODE <= 1) {
                    *(float2*)(Cf + (long)r * F + col) = make_float2(v0, v1);
                } else {
                    __nv_bfloat16 h0, l0, h1, l1;
                    split_bf16(v0, h0, l0);
                    split_bf16(v1, h1, l1);
                    *(__nv_bfloat162*)(Ch + (long)r * F + col) = __nv_bfloat162(h0, h1);
                    *(__nv_bfloat162*)(Cl + (long)r * F + col) = __nv_bfloat162(l0, l1);
                }
            }
        }
    }
}

// ---------------------------------------------------------------------------
// fp32 SGEMM (layers 1 and 6, tiny K/F)
// ---------------------------------------------------------------------------
#define BM 128
#define BK 16
template <int BN_, bool FUSE>
__global__ __launch_bounds__(16 * (BN_ / 8)) void sgemm_kernel(
    const float* __restrict__ A, const float* __restrict__ B,
    const float* __restrict__ bias, float* __restrict__ C,
    int M, int K, int F)
{
    constexpr int TX = BN_ / 8;
    constexpr int NT = 16 * TX;
    __shared__ float As[BK][BM + 4];
    __shared__ float Bs[BK][BN_];
    int tid = threadIdx.x;
    int tx = tid % TX, ty = tid / TX;
    int row0 = blockIdx.y * BM, col0 = blockIdx.x * BN_;
    float acc[8][8] = {};
    for (int kt = 0; kt < K; kt += BK) {
        #pragma unroll
        for (int idx = tid; idx < BM * BK; idx += NT) {
            int m = idx / BK, k = idx % BK;
            int gr = row0 + m, gk = kt + k;
            As[k][m] = (gr < M && gk < K) ? A[(long)gr * K + gk] : 0.0f;
        }
        #pragma unroll
        for (int idx = tid; idx < BK * BN_; idx += NT) {
            int k = idx / BN_, n = idx % BN_;
            int gk = kt + k, gc = col0 + n;
            Bs[k][n] = (gk < K && gc < F) ? B[(long)gk * F + gc] : 0.0f;
        }
        __syncthreads();
        #pragma unroll
        for (int k = 0; k < BK; k++) {
            float a[8], b[8];
            *(float4*)&a[0] = *(const float4*)&As[k][ty * 8];
            *(float4*)&a[4] = *(const float4*)&As[k][ty * 8 + 4];
            *(float4*)&b[0] = *(const float4*)&Bs[k][tx * 8];
            *(float4*)&b[4] = *(const float4*)&Bs[k][tx * 8 + 4];
            #pragma unroll
            for (int i = 0; i < 8; i++)
                #pragma unroll
                for (int j = 0; j < 8; j++)
                    acc[i][j] += a[i] * b[j];
        }
        __syncthreads();
    }
    #pragma unroll
    for (int i = 0; i < 8; i++) {
        int r = row0 + ty * 8 + i;
        if (r >= M) continue;
        #pragma unroll
        for (int j = 0; j < 8; j++) {
            int c = col0 + tx * 8 + j;
            if (c < F) {
                float v = acc[i][j];
                if (FUSE) v = fmaxf(v + bias[c], 0.0f);
                C[(long)r * F + c] = v;
            }
        }
    }
}

// ---------------------------------------------------------------------------
// Driver (plain stream-0, serial)
// ---------------------------------------------------------------------------
#define GATHER_GRID 6250
#define HMMA256_SMEM (2 * (2 * 128 * 128 + 2 * 256 * 128))   // 196608
#define HMMA_SMEM_64 (3 * (2 * 128 * 128 + 2 * 64 * 128))    // 147456

extern "C" void kernel_launch(void* const* d_in, const int* in_sizes, int n_in,
                              void* d_out, int out_size)
{
    const float* x  = (const float*)d_in[0];
    const int* eidx = (const int*)d_in[1];
    const int* src  = eidx;
    const int* dst  = eidx + NE;
    const float* W[6];
    const float* b[6];
    for (int i = 0; i < 6; i++) {
        W[i] = (const float*)d_in[2 + 2 * i];
        b[i] = (const float*)d_in[3 + 2 * i];
    }

    float *d_x, *d_t, *d_dinv, *d_enorm;
    __nv_bfloat16 *d_xh, *d_xl, *d_th, *d_tl;
    int *d_cnt, *d_rowptr, *d_cursor, *d_esrc, *d_bsum;
    __nv_bfloat16 *w2h, *w2l, *w3h, *w3l, *w4h, *w4l, *w5h, *w5l;
    cudaGetSymbolAddress((void**)&d_x, g_x);
    cudaGetSymbolAddress((void**)&d_t, g_t);
    cudaGetSymbolAddress((void**)&d_xh, g_xh);
    cudaGetSymbolAddress((void**)&d_xl, g_xl);
    cudaGetSymbolAddress((void**)&d_th, g_th);
    cudaGetSymbolAddress((void**)&d_tl, g_tl);
    cudaGetSymbolAddress((void**)&d_dinv, g_dinv);
    cudaGetSymbolAddress((void**)&d_cnt, g_cnt);
    cudaGetSymbolAddress((void**)&d_rowptr, g_rowptr);
    cudaGetSymbolAddress((void**)&d_cursor, g_cursor);
    cudaGetSymbolAddress((void**)&d_esrc, g_esrc);
    cudaGetSymbolAddress((void**)&d_enorm, g_enorm);
    cudaGetSymbolAddress((void**)&d_bsum, g_bsum);
    cudaGetSymbolAddress((void**)&w2h, g_w2h); cudaGetSymbolAddress((void**)&w2l, g_w2l);
    cudaGetSymbolAddress((void**)&w3h, g_w3h); cudaGetSymbolAddress((void**)&w3l, g_w3l);
    cudaGetSymbolAddress((void**)&w4h, g_w4h); cudaGetSymbolAddress((void**)&w4l, g_w4l);
    cudaGetSymbolAddress((void**)&w5h, g_w5h); cudaGetSymbolAddress((void**)&w5l, g_w5l);

    cudaFuncSetAttribute(hmma256_kernel<0>, cudaFuncAttributeMaxDynamicSharedMemorySize, HMMA256_SMEM);
    cudaFuncSetAttribute(hmma256_kernel<1>, cudaFuncAttributeMaxDynamicSharedMemorySize, HMMA256_SMEM);
    cudaFuncSetAttribute(hmma256_kernel<2>, cudaFuncAttributeMaxDynamicSharedMemorySize, HMMA256_SMEM);
    cudaFuncSetAttribute(hmma_gemm_kernel<64, 0>, cudaFuncAttributeMaxDynamicSharedMemorySize, HMMA_SMEM_64);

    // --- weight transpose + bf16 split (dependency-free, first) ---
    wsplit_all_kernel<<<288, dim3(32, 8)>>>(W[1], W[2], W[3], W[4],
                                            w2h, w2l, w3h, w3l, w4h, w4l, w5h, w5l);

    // --- CSR + norm precompute ---
    cudaMemsetAsync(d_cnt, 0, NN * sizeof(int));
    cnt_acc_kernel<<<(NE + 255) / 256, 256>>>(dst, d_cnt);
    scan1_kernel<<<SCAN_BLOCKS, 1024>>>(d_cnt, d_rowptr, d_bsum, d_dinv);
    scan23_kernel<<<SCAN_BLOCKS, 1024>>>(d_rowptr, d_bsum, d_cursor);
    fill_kernel<<<(NE + 255) / 256, 256>>>(src, dst, d_dinv, d_cursor, d_esrc, d_enorm);

    const int MT = (NN + 127) / 128;

    // L1 (pre-agg, 35->64, fp32): t = Agg(x); x = relu(t@W1+b1)
    gather_kernel<35, false, false><<<GATHER_GRID, 256>>>(d_rowptr, d_esrc, d_enorm, x, d_dinv, nullptr, d_t);
    { dim3 g(1, MT); sgemm_kernel<64, true><<<g, 128>>>(d_t, W[0], b[0], d_x, NN, 35, 64); }

    // L2 (pre-agg, 64->256): gather splits -> hmma256 (bias+relu, fp32 out)
    gather64_kernel<false, false, 1><<<GATHER_GRID, 256>>>(d_rowptr, d_esrc, d_enorm, d_x, d_dinv, nullptr, nullptr, d_th, d_tl);
    { dim3 g(1, MT); hmma256_kernel<1><<<g, 256, HMMA256_SMEM>>>(d_th, d_tl, w2h, w2l, b[1], d_x, nullptr, nullptr, NN, 64, 256); }

    // L3 (pre-agg, 256->512): gather splits -> hmma256 (bias+relu, bf16-split out)
    gather256_kernel<false, false, 1><<<GATHER_GRID, 256>>>(d_rowptr, d_esrc, d_enorm, d_x, d_dinv, nullptr, nullptr, d_th, d_tl);
    { dim3 g(2, MT); hmma256_kernel<2><<<g, 256, HMMA256_SMEM>>>(d_th, d_tl, w3h, w3l, b[2], nullptr, d_xh, d_xl, NN, 256, 512); }

    // L4 (post-agg, 512->256): hmma256 (fp32 out) -> gather (bias+relu, split out)
    { dim3 g(1, MT); hmma256_kernel<0><<<g, 256, HMMA256_SMEM>>>(d_xh, d_xl, w4h, w4l, nullptr, d_t, nullptr, nullptr, NN, 512, 256); }
    gather256_kernel<true, true, 1><<<GATHER_GRID, 256>>>(d_rowptr, d_esrc, d_enorm, d_t, d_dinv, b[3], nullptr, d_th, d_tl);

    // L5 (post-agg, 256->64): hmma BN=64 (fp32 out) -> gather (bias+relu, fp32 out)
    { dim3 g(1, MT); hmma_gemm_kernel<64, 0><<<g, 256, HMMA_SMEM_64>>>(d_th, d_tl, w5h, w5l, nullptr, d_t, nullptr, nullptr, NN, 256, 64); }
    gather64_kernel<true, true, 0><<<GATHER_GRID, 256>>>(d_rowptr, d_esrc, d_enorm, d_t, d_dinv, b[4], d_x, nullptr, nullptr);

    // L6 (post-agg, 64->16, fp32, no relu) -> d_out
    { dim3 g(1, MT); sgemm_kernel<64, false><<<g, 128>>>(d_x, W[5], nullptr, d_t, NN, 64, 16); }
    gather_kernel<16, true, false><<<GATHER_GRID, 256>>>(d_rowptr, d_esrc, d_enorm, d_t, d_dinv, b[5], (float*)d_out);
}

// round 15
// speedup vs baseline: 1.4294x; 1.4294x over previous
#include <cuda_runtime.h>
#include <cuda_bf16.h>
#include <cstdint>

#define NN 50000
#define NE 800000
#define MAXF 512

// ---------------------------------------------------------------------------
// Scratch (__device__ globals per harness allocation rules)
// ---------------------------------------------------------------------------
__device__ float g_x[NN * MAXF];
__device__ float g_t[NN * MAXF];
__device__ __nv_bfloat16 g_xh[NN * MAXF], g_xl[NN * MAXF];
__device__ __nv_bfloat16 g_th[NN * MAXF], g_tl[NN * MAXF];
__device__ float g_dinv[NN];
__device__ int   g_cnt[NN];
__device__ int   g_rowptr[NN + 1];
__device__ int   g_cursor[NN];
__device__ int   g_esrc[NE];
__device__ float g_enorm[NE];
__device__ int   g_bsum[64];
__device__ __nv_bfloat16 g_w2h[256 * 64],  g_w2l[256 * 64];
__device__ __nv_bfloat16 g_w3h[512 * 256], g_w3l[512 * 256];
__device__ __nv_bfloat16 g_w4h[256 * 512], g_w4l[256 * 512];
__device__ __nv_bfloat16 g_w5h[64 * 256],  g_w5l[64 * 256];

// ---------------------------------------------------------------------------
// helpers
// ---------------------------------------------------------------------------
__device__ __forceinline__ uint32_t smem_u32(const void* p) {
    uint32_t a;
    asm("{ .reg .u64 t; cvta.to.shared.u64 t, %1; cvt.u32.u64 %0, t; }" : "=r"(a) : "l"(p));
    return a;
}
__device__ __forceinline__ void cp16(uint32_t dst, const void* src) {
    asm volatile("cp.async.cg.shared.global [%0], [%1], 16;" :: "r"(dst), "l"(src) : "memory");
}
#define CP_COMMIT() asm volatile("cp.async.commit_group;" ::: "memory")

#define LDSM4(r0, r1, r2, r3, addr) \
    asm volatile("ldmatrix.sync.aligned.m8n8.x4.shared.b16 {%0,%1,%2,%3}, [%4];" \
                 : "=r"(r0), "=r"(r1), "=r"(r2), "=r"(r3) : "r"(addr))

__device__ __forceinline__ void mma_bf16(float* d, const uint32_t* a, uint32_t b0, uint32_t b1) {
    asm volatile("mma.sync.aligned.m16n8k16.row.col.f32.bf16.bf16.f32 "
                 "{%0,%1,%2,%3}, {%4,%5,%6,%7}, {%8,%9}, {%0,%1,%2,%3};"
                 : "+f"(d[0]), "+f"(d[1]), "+f"(d[2]), "+f"(d[3])
                 : "r"(a[0]), "r"(a[1]), "r"(a[2]), "r"(a[3]), "r"(b0), "r"(b1));
}

__device__ __forceinline__ void split_bf16(float v, __nv_bfloat16& h, __nv_bfloat16& l) {
    h = __float2bfloat16(v);
    l = __float2bfloat16(v - __bfloat162float(h));
}

// ---------------------------------------------------------------------------
// CSR build: count -> scan1 (fused dinv) -> scan23 -> fill
// ---------------------------------------------------------------------------
__global__ void cnt_acc_kernel(const int* __restrict__ dst, int* cnt) {
    int e = blockIdx.x * blockDim.x + threadIdx.x;
    if (e < NE) atomicAdd(&cnt[dst[e]], 1);
}
#define SCAN_BLOCKS ((NN + 1023) / 1024)
__global__ __launch_bounds__(1024) void scan1_kernel(const int* __restrict__ cnt,
                                                     int* rowptr, int* bsum, float* dinv) {
    __shared__ int s[1024];
    int i = blockIdx.x * 1024 + threadIdx.x;
    int v = (i < NN) ? cnt[i] : 0;
    if (i < NN) dinv[i] = rsqrtf((float)(v + 1));
    s[threadIdx.x] = v;
    __syncthreads();
    for (int off = 1; off < 1024; off <<= 1) {
        int t = (threadIdx.x >= off) ? s[threadIdx.x - off] : 0;
        __syncthreads();
        if (threadIdx.x >= off) s[threadIdx.x] += t;
        __syncthreads();
    }
    if (i < NN) rowptr[i] = s[threadIdx.x] - v;
    if (threadIdx.x == 1023) bsum[blockIdx.x] = s[1023];
}
__global__ __launch_bounds__(1024) void scan23_kernel(int* rowptr, const int* __restrict__ bsum,
                                                      int* cursor) {
    __shared__ int spre;
    if (threadIdx.x == 0) {
        int run = 0;
        for (int b = 0; b < blockIdx.x; b++) run += bsum[b];
        spre = run;
        if (blockIdx.x == SCAN_BLOCKS - 1)
            rowptr[NN] = run + bsum[SCAN_BLOCKS - 1];
    }
    __syncthreads();
    int pre = spre;
    int i = blockIdx.x * 1024 + threadIdx.x;
    if (i < NN) { int r = rowptr[i] + pre; rowptr[i] = r; cursor[i] = r; }
}
__global__ void fill_kernel(const int* __restrict__ src, const int* __restrict__ dst,
                            const float* __restrict__ dinv,
                            int* cursor, int* esrc, float* enorm) {
    int e = blockIdx.x * blockDim.x + threadIdx.x;
    if (e >= NE) return;
    int s = src[e], d = dst[e];
    int pos = atomicAdd(&cursor[d], 1);
    esrc[pos] = s;
    enorm[pos] = dinv[s] * dinv[d];
}

// ---------------------------------------------------------------------------
// Merged weight transpose + bf16 hi/lo split (all 4 weights, one launch)
// ---------------------------------------------------------------------------
__global__ void wsplit_all_kernel(const float* __restrict__ W2, const float* __restrict__ W3,
                                  const float* __restrict__ W4, const float* __restrict__ W5,
                                  __nv_bfloat16* o2h, __nv_bfloat16* o2l,
                                  __nv_bfloat16* o3h, __nv_bfloat16* o3l,
                                  __nv_bfloat16* o4h, __nv_bfloat16* o4l,
                                  __nv_bfloat16* o5h, __nv_bfloat16* o5l) {
    int bid = blockIdx.x;
    const float* W; __nv_bfloat16 *Th, *Tl;
    int K, F, t, fx;
    if (bid < 16)       { W = W2; Th = o2h; Tl = o2l; K = 64;  F = 256; t = bid;       fx = 8;  }
    else if (bid < 144) { W = W3; Th = o3h; Tl = o3l; K = 256; F = 512; t = bid - 16;  fx = 16; }
    else if (bid < 272) { W = W4; Th = o4h; Tl = o4l; K = 512; F = 256; t = bid - 144; fx = 8;  }
    else                { W = W5; Th = o5h; Tl = o5l; K = 256; F = 64;  t = bid - 272; fx = 2;  }
    int f0 = (t % fx) * 32, k0 = (t / fx) * 32;

    __shared__ float tile[32][33];
    for (int i = threadIdx.y; i < 32; i += 8) {
        int k = k0 + i, f = f0 + threadIdx.x;
        tile[i][threadIdx.x] = W[(long)k * F + f];
    }
    __syncthreads();
    for (int i = threadIdx.y; i < 32; i += 8) {
        int f = f0 + i, k = k0 + threadIdx.x;
        __nv_bfloat16 h, l;
        split_bf16(tile[threadIdx.x][i], h, l);
        Th[(long)f * K + k] = h;
        Tl[(long)f * K + k] = l;
    }
}

// ---------------------------------------------------------------------------
// Vectorized gather F=256: 1 warp per node, 2 float4 per lane.
// ---------------------------------------------------------------------------
template <bool BIAS, bool RELU, int OUT>
__global__ __launch_bounds__(256) void gather256_kernel(
    const int* __restrict__ rowptr, const int* __restrict__ esrc,
    const float* __restrict__ enorm, const float* __restrict__ in,
    const float* __restrict__ dinv, const float* __restrict__ bias,
    float* __restrict__ out, __nv_bfloat16* __restrict__ oh, __nv_bfloat16* __restrict__ ol)
{
    int gw = (blockIdx.x * blockDim.x + threadIdx.x) >> 5;
    int lane = threadIdx.x & 31;
    if (gw >= NN) return;

    float di = dinv[gw];
    float selfw = di * di;
    const float4* self = (const float4*)(in + (long)gw * 256);
    float4 a0 = self[lane], a1 = self[32 + lane];
    float4 acc0 = make_float4(a0.x * selfw, a0.y * selfw, a0.z * selfw, a0.w * selfw);
    float4 acc1 = make_float4(a1.x * selfw, a1.y * selfw, a1.z * selfw, a1.w * selfw);

    int e0 = rowptr[gw], e1 = rowptr[gw + 1];
    for (int e = e0; e < e1; e++) {
        int s = esrc[e];
        float nv = enorm[e];
        const float4* r = (const float4*)(in + (long)s * 256);
        float4 h0 = r[lane], h1 = r[32 + lane];
        acc0.x += h0.x * nv; acc0.y += h0.y * nv; acc0.z += h0.z * nv; acc0.w += h0.w * nv;
        acc1.x += h1.x * nv; acc1.y += h1.y * nv; acc1.z += h1.z * nv; acc1.w += h1.w * nv;
    }

    if (BIAS) {
        float4 b0 = ((const float4*)bias)[lane], b1 = ((const float4*)bias)[32 + lane];
        acc0.x += b0.x; acc0.y += b0.y; acc0.z += b0.z; acc0.w += b0.w;
        acc1.x += b1.x; acc1.y += b1.y; acc1.z += b1.z; acc1.w += b1.w;
    }
    if (RELU) {
        acc0.x = fmaxf(acc0.x, 0.f); acc0.y = fmaxf(acc0.y, 0.f);
        acc0.z = fmaxf(acc0.z, 0.f); acc0.w = fmaxf(acc0.w, 0.f);
        acc1.x = fmaxf(acc1.x, 0.f); acc1.y = fmaxf(acc1.y, 0.f);
        acc1.z = fmaxf(acc1.z, 0.f); acc1.w = fmaxf(acc1.w, 0.f);
    }
    if (OUT == 0) {
        float4* o = (float4*)(out + (long)gw * 256);
        o[lane] = acc0; o[32 + lane] = acc1;
    } else {
        float v[8] = {acc0.x, acc0.y, acc0.z, acc0.w, acc1.x, acc1.y, acc1.z, acc1.w};
        #pragma unroll
        for (int q = 0; q < 2; q++) {
            long base = (long)gw * 256 + (q ? 128 : 0) + lane * 4;
            __nv_bfloat16 h0, l0, h1, l1, h2, l2, h3, l3;
            split_bf16(v[q * 4 + 0], h0, l0); split_bf16(v[q * 4 + 1], h1, l1);
            split_bf16(v[q * 4 + 2], h2, l2); split_bf16(v[q * 4 + 3], h3, l3);
            *(__nv_bfloat162*)(oh + base)     = __nv_bfloat162(h0, h1);
            *(__nv_bfloat162*)(oh + base + 2) = __nv_bfloat162(h2, h3);
            *(__nv_bfloat162*)(ol + base)     = __nv_bfloat162(l0, l1);
            *(__nv_bfloat162*)(ol + base + 2) = __nv_bfloat162(l2, l3);
        }
    }
}

// ---------------------------------------------------------------------------
// Vectorized gather F=64: 1 warp per node, float2 per lane.
// ---------------------------------------------------------------------------
template <bool BIAS, bool RELU, int OUT>
__global__ __launch_bounds__(256) void gather64_kernel(
    const int* __restrict__ rowptr, const int* __restrict__ esrc,
    const float* __restrict__ enorm, const float* __restrict__ in,
    const float* __restrict__ dinv, const float* __restrict__ bias,
    float* __restrict__ out, __nv_bfloat16* __restrict__ oh, __nv_bfloat16* __restrict__ ol)
{
    int gw = (blockIdx.x * blockDim.x + threadIdx.x) >> 5;
    int lane = threadIdx.x & 31;
    if (gw >= NN) return;

    float di = dinv[gw];
    float selfw = di * di;
    float2 a = ((const float2*)(in + (long)gw * 64))[lane];
    float2 acc = make_float2(a.x * selfw, a.y * selfw);

    int e0 = rowptr[gw], e1 = rowptr[gw + 1];
    for (int e = e0; e < e1; e++) {
        int s = esrc[e];
        float nv = enorm[e];
        float2 h = ((const float2*)(in + (long)s * 64))[lane];
        acc.x += h.x * nv; acc.y += h.y * nv;
    }

    if (BIAS) {
        float2 bb = ((const float2*)bias)[lane];
        acc.x += bb.x; acc.y += bb.y;
    }
    if (RELU) { acc.x = fmaxf(acc.x, 0.f); acc.y = fmaxf(acc.y, 0.f); }
    if (OUT == 0) {
        ((float2*)(out + (long)gw * 64))[lane] = acc;
    } else {
        __nv_bfloat16 h0, l0, h1, l1;
        split_bf16(acc.x, h0, l0); split_bf16(acc.y, h1, l1);
        *(__nv_bfloat162*)(oh + (long)gw * 64 + lane * 2) = __nv_bfloat162(h0, h1);
        *(__nv_bfloat162*)(ol + (long)gw * 64 + lane * 2) = __nv_bfloat162(l0, l1);
    }
}

// ---------------------------------------------------------------------------
// Generic scalar gather (F=35, F=16)
// ---------------------------------------------------------------------------
template <int F, bool BIAS, bool RELU>
__global__ __launch_bounds__(256) void gather_kernel(
    const int* __restrict__ rowptr, const int* __restrict__ esrc,
    const float* __restrict__ enorm, const float* __restrict__ in,
    const float* __restrict__ dinv, const float* __restrict__ bias,
    float* __restrict__ out)
{
    int gw = (blockIdx.x * blockDim.x + threadIdx.x) >> 5;
    int lane = threadIdx.x & 31;
    if (gw >= NN) return;
    constexpr int FPL = (F + 31) / 32;

    float acc[FPL];
    float di = dinv[gw];
    float selfw = di * di;
    const float* hd = &in[(long)gw * F];
    #pragma unroll
    for (int i = 0; i < FPL; i++) {
        int f = lane + 32 * i;
        acc[i] = (f < F) ? hd[f] * selfw : 0.0f;
    }
    int e0 = rowptr[gw], e1 = rowptr[gw + 1];
    for (int e = e0; e < e1; e++) {
        int s = esrc[e];
        float nv = enorm[e];
        const float* hs = &in[(long)s * F];
        #pragma unroll
        for (int i = 0; i < FPL; i++) {
            int f = lane + 32 * i;
            if (f < F) acc[i] += hs[f] * nv;
        }
    }
    float* o = &out[(long)gw * F];
    #pragma unroll
    for (int i = 0; i < FPL; i++) {
        int f = lane + 32 * i;
        if (f < F) {
            float v = acc[i];
            if (BIAS) v += bias[f];
            if (RELU) v = fmaxf(v, 0.0f);
            o[f] = v;
        }
    }
}

// ---------------------------------------------------------------------------
// bf16 split-precision mma.sync GEMM, 3-stage cp.async pipeline, SW128 swizzle.
// D += Ah*Bh + Al*Bh + Ah*Bl
// ---------------------------------------------------------------------------
#define SWZ(row, byteoff) (((row) * 128 + (byteoff)) ^ (((row) & 7) << 4))

template <int BN, int MODE>
__global__ __launch_bounds__(256) void hmma_gemm_kernel(
    const __nv_bfloat16* __restrict__ Ah, const __nv_bfloat16* __restrict__ Al,
    const __nv_bfloat16* __restrict__ Bh, const __nv_bfloat16* __restrict__ Bl,
    const float* __restrict__ bias,
    float* __restrict__ Cf, __nv_bfloat16* __restrict__ Ch, __nv_bfloat16* __restrict__ Cl,
    int M, int K, int F)
{
    constexpr int WARPS_N = (BN == 128) ? 4 : 2;
    constexpr int WARPS_M = 8 / WARPS_N;
    constexpr int WM = 128 / WARPS_M;
    constexpr int MI = WM / 16;
    constexpr uint32_t A_HI = 0;
    constexpr uint32_t A_LO = 128 * 128;
    constexpr uint32_t B_HI = 2 * 128 * 128;
    constexpr uint32_t B_LO = B_HI + BN * 128;
    constexpr uint32_t STAGE = B_LO + BN * 128;

    extern __shared__ char smem[];
    uint32_t sb = smem_u32(smem);
    int tid = threadIdx.x;
    int wid = tid >> 5, lane = tid & 31;
    int wm = wid % WARPS_M, wn = wid / WARPS_M;
    int m0 = blockIdx.y * 128, n0 = blockIdx.x * BN;
    int lr = lane & 15, lc = lane >> 4;

    float acc[MI][4][4] = {};

    auto load_stage = [&](int kt, int st) {
        uint32_t s0 = sb + st * STAGE;
        long kbase = (long)kt * 64;
        #pragma unroll
        for (int i = 0; i < 4; i++) {
            int idx = tid + i * 256;
            int row = idx >> 3, c = idx & 7;
            int gr = m0 + row; if (gr >= M) gr = M - 1;
            long off = (long)gr * K + kbase + c * 8;
            uint32_t sw = SWZ(row, c * 16);
            cp16(s0 + A_HI + sw, Ah + off);
            cp16(s0 + A_LO + sw, Al + off);
        }
        #pragma unroll
        for (int i = 0; i < BN / 32; i++) {
            int idx = tid + i * 256;
            int row = idx >> 3, c = idx & 7;
            long off = (long)(n0 + row) * K + kbase + c * 8;
            uint32_t sw = SWZ(row, c * 16);
            cp16(s0 + B_HI + sw, Bh + off);
            cp16(s0 + B_LO + sw, Bl + off);
        }
    };

    int nkt = K >> 6;
    load_stage(0, 0); CP_COMMIT();
    if (nkt > 1) { load_stage(1, 1); CP_COMMIT(); }

    for (int kt = 0; kt < nkt; kt++) {
        if (kt + 1 < nkt) {
            asm volatile("cp.async.wait_group 1;" ::: "memory");
        } else {
            asm volatile("cp.async.wait_group 0;" ::: "memory");
        }
        __syncthreads();
        if (kt + 2 < nkt) { load_stage(kt + 2, (kt + 2) % 3); CP_COMMIT(); }

        uint32_t s0 = sb + (kt % 3) * STAGE;
        #pragma unroll
        for (int k16 = 0; k16 < 4; k16++) {
            int koff = k16 * 32 + lc * 16;
            uint32_t afh[MI][4], afl[MI][4];
            #pragma unroll
            for (int mi = 0; mi < MI; mi++) {
                int row = wm * WM + mi * 16 + lr;
                uint32_t sw = SWZ(row, koff);
                LDSM4(afh[mi][0], afh[mi][1], afh[mi][2], afh[mi][3], s0 + A_HI + sw);
                LDSM4(afl[mi][0], afl[mi][1], afl[mi][2], afl[mi][3], s0 + A_LO + sw);
            }
            uint32_t bfh[2][4], bfl[2][4];
            #pragma unroll
            for (int g = 0; g < 2; g++) {
                int row = wn * 32 + g * 16 + lr;
                uint32_t sw = SWZ(row, koff);
                LDSM4(bfh[g][0], bfh[g][1], bfh[g][2], bfh[g][3], s0 + B_HI + sw);
                LDSM4(bfl[g][0], bfl[g][1], bfl[g][2], bfl[g][3], s0 + B_LO + sw);
            }
            #pragma unroll
            for (int mi = 0; mi < MI; mi++) {
                #pragma unroll
                for (int j = 0; j < 4; j++) {
                    int g = j >> 1, h = j & 1;
                    uint32_t b0 = bfh[g][h], b1 = bfh[g][h + 2];
                    mma_bf16(acc[mi][j], afh[mi], b0, b1);
                    mma_bf16(acc[mi][j], afl[mi], b0, b1);
                    mma_bf16(acc[mi][j], afh[mi], bfl[g][h], bfl[g][h + 2]);
                }
            }
        }
        __syncthreads();
    }

    #pragma unroll
    for (int mi = 0; mi < MI; mi++) {
        #pragma unroll
        for (int j = 0; j < 4; j++) {
            int r0 = m0 + wm * WM + mi * 16 + (lane >> 2);
            int col = n0 + wn * 32 + j * 8 + (lane & 3) * 2;
            #pragma unroll
            for (int half = 0; half < 2; half++) {
                int r = r0 + half * 8;
                if (r >= M) continue;
                float v0 = acc[mi][j][half * 2 + 0];
                float v1 = acc[mi][j][half * 2 + 1];
                if (MODE >= 1) {
                    v0 = fmaxf(v0 + bias[col], 0.0f);
                    v1 = fmaxf(v1 + bias[col + 1], 0.0f);
                }
                if (MODE <= 1) {
                    *(float2*)(Cf + (long)r * F + col) = make_float2(v0, v1);
                } else {
                    __nv_bfloat16 h0, l0, h1, l1;
                    split_bf16(v0, h0, l0);
                    split_bf16(v1, h1, l1);
                    *(__nv_bfloat162*)(Ch + (long)r * F + col) = __nv_bfloat162(h0, h1);
                    *(__nv_bfloat162*)(Cl + (long)r * F + col) = __nv_bfloat162(l0, l1);
                }
            }
        }
    }
}

// ---------------------------------------------------------------------------
// fp32 SGEMM (layers 1 and 6, tiny K/F)
// ---------------------------------------------------------------------------
#define BM 128
#define BK 16
template <int BN_, bool FUSE>
__global__ __launch_bounds__(16 * (BN_ / 8)) void sgemm_kernel(
    const float* __restrict__ A, const float* __restrict__ B,
    const float* __restrict__ bias, float* __restrict__ C,
    int M, int K, int F)
{
    constexpr int TX = BN_ / 8;
    constexpr int NT = 16 * TX;
    __shared__ float As[BK][BM + 4];
    __shared__ float Bs[BK][BN_];
    int tid = threadIdx.x;
    int tx = tid % TX, ty = tid / TX;
    int row0 = blockIdx.y * BM, col0 = blockIdx.x * BN_;
    float acc[8][8] = {};
    for (int kt = 0; kt < K; kt += BK) {
        #pragma unroll
        for (int idx = tid; idx < BM * BK; idx += NT) {
            int m = idx / BK, k = idx % BK;
            int gr = row0 + m, gk = kt + k;
            As[k][m] = (gr < M && gk < K) ? A[(long)gr * K + gk] : 0.0f;
        }
        #pragma unroll
        for (int idx = tid; idx < BK * BN_; idx += NT) {
            int k = idx / BN_, n = idx % BN_;
            int gk = kt + k, gc = col0 + n;
            Bs[k][n] = (gk < K && gc < F) ? B[(long)gk * F + gc] : 0.0f;
        }
        __syncthreads();
        #pragma unroll
        for (int k = 0; k < BK; k++) {
            float a[8], b[8];
            *(float4*)&a[0] = *(const float4*)&As[k][ty * 8];
            *(float4*)&a[4] = *(const float4*)&As[k][ty * 8 + 4];
            *(float4*)&b[0] = *(const float4*)&Bs[k][tx * 8];
            *(float4*)&b[4] = *(const float4*)&Bs[k][tx * 8 + 4];
            #pragma unroll
            for (int i = 0; i < 8; i++)
                #pragma unroll
                for (int j = 0; j < 8; j++)
                    acc[i][j] += a[i] * b[j];
        }
        __syncthreads();
    }
    #pragma unroll
    for (int i = 0; i < 8; i++) {
        int r = row0 + ty * 8 + i;
        if (r >= M) continue;
        #pragma unroll
        for (int j = 0; j < 8; j++) {
            int c = col0 + tx * 8 + j;
            if (c < F) {
                float v = acc[i][j];
                if (FUSE) v = fmaxf(v + bias[c], 0.0f);
                C[(long)r * F + c] = v;
            }
        }
    }
}

// ---------------------------------------------------------------------------
// Driver (plain stream-0, serial) — R13 configuration
// ---------------------------------------------------------------------------
#define GATHER_GRID 6250
#define HMMA_SMEM_128 (3 * (2 * 128 * 128 + 2 * 128 * 128))   // 196608
#define HMMA_SMEM_64  (3 * (2 * 128 * 128 + 2 * 64 * 128))    // 147456

extern "C" void kernel_launch(void* const* d_in, const int* in_sizes, int n_in,
                              void* d_out, int out_size)
{
    const float* x  = (const float*)d_in[0];
    const int* eidx = (const int*)d_in[1];
    const int* src  = eidx;
    const int* dst  = eidx + NE;
    const float* W[6];
    const float* b[6];
    for (int i = 0; i < 6; i++) {
        W[i] = (const float*)d_in[2 + 2 * i];
        b[i] = (const float*)d_in[3 + 2 * i];
    }

    float *d_x, *d_t, *d_dinv, *d_enorm;
    __nv_bfloat16 *d_xh, *d_xl, *d_th, *d_tl;
    int *d_cnt, *d_rowptr, *d_cursor, *d_esrc, *d_bsum;
    __nv_bfloat16 *w2h, *w2l, *w3h, *w3l, *w4h, *w4l, *w5h, *w5l;
    cudaGetSymbolAddress((void**)&d_x, g_x);
    cudaGetSymbolAddress((void**)&d_t, g_t);
    cudaGetSymbolAddress((void**)&d_xh, g_xh);
    cudaGetSymbolAddress((void**)&d_xl, g_xl);
    cudaGetSymbolAddress((void**)&d_th, g_th);
    cudaGetSymbolAddress((void**)&d_tl, g_tl);
    cudaGetSymbolAddress((void**)&d_dinv, g_dinv);
    cudaGetSymbolAddress((void**)&d_cnt, g_cnt);
    cudaGetSymbolAddress((void**)&d_rowptr, g_rowptr);
    cudaGetSymbolAddress((void**)&d_cursor, g_cursor);
    cudaGetSymbolAddress((void**)&d_esrc, g_esrc);
    cudaGetSymbolAddress((void**)&d_enorm, g_enorm);
    cudaGetSymbolAddress((void**)&d_bsum, g_bsum);
    cudaGetSymbolAddress((void**)&w2h, g_w2h); cudaGetSymbolAddress((void**)&w2l, g_w2l);
    cudaGetSymbolAddress((void**)&w3h, g_w3h); cudaGetSymbolAddress((void**)&w3l, g_w3l);
    cudaGetSymbolAddress((void**)&w4h, g_w4h); cudaGetSymbolAddress((void**)&w4l, g_w4l);
    cudaGetSymbolAddress((void**)&w5h, g_w5h); cudaGetSymbolAddress((void**)&w5l, g_w5l);

    cudaFuncSetAttribute(hmma_gemm_kernel<128, 0>, cudaFuncAttributeMaxDynamicSharedMemorySize, HMMA_SMEM_128);
    cudaFuncSetAttribute(hmma_gemm_kernel<128, 1>, cudaFuncAttributeMaxDynamicSharedMemorySize, HMMA_SMEM_128);
    cudaFuncSetAttribute(hmma_gemm_kernel<128, 2>, cudaFuncAttributeMaxDynamicSharedMemorySize, HMMA_SMEM_128);
    cudaFuncSetAttribute(hmma_gemm_kernel<64, 0>,  cudaFuncAttributeMaxDynamicSharedMemorySize, HMMA_SMEM_64);

    // --- weight transpose + bf16 split (dependency-free, first) ---
    wsplit_all_kernel<<<288, dim3(32, 8)>>>(W[1], W[2], W[3], W[4],
                                            w2h, w2l, w3h, w3l, w4h, w4l, w5h, w5l);

    // --- CSR + norm precompute ---
    cudaMemsetAsync(d_cnt, 0, NN * sizeof(int));
    cnt_acc_kernel<<<(NE + 255) / 256, 256>>>(dst, d_cnt);
    scan1_kernel<<<SCAN_BLOCKS, 1024>>>(d_cnt, d_rowptr, d_bsum, d_dinv);
    scan23_kernel<<<SCAN_BLOCKS, 1024>>>(d_rowptr, d_bsum, d_cursor);
    fill_kernel<<<(NE + 255) / 256, 256>>>(src, dst, d_dinv, d_cursor, d_esrc, d_enorm);

    const int MT = (NN + 127) / 128;

    // L1 (pre-agg, 35->64, fp32): t = Agg(x); x = relu(t@W1+b1)
    gather_kernel<35, false, false><<<GATHER_GRID, 256>>>(d_rowptr, d_esrc, d_enorm, x, d_dinv, nullptr, d_t);
    { dim3 g(1, MT); sgemm_kernel<64, true><<<g, 128>>>(d_t, W[0], b[0], d_x, NN, 35, 64); }

    // L2 (pre-agg, 64->256): gather splits -> hmma (bias+relu, fp32 out)
    gather64_kernel<false, false, 1><<<GATHER_GRID, 256>>>(d_rowptr, d_esrc, d_enorm, d_x, d_dinv, nullptr, nullptr, d_th, d_tl);
    { dim3 g(2, MT); hmma_gemm_kernel<128, 1><<<g, 256, HMMA_SMEM_128>>>(d_th, d_tl, w2h, w2l, b[1], d_x, nullptr, nullptr, NN, 64, 256); }

    // L3 (pre-agg, 256->512): gather splits -> hmma (bias+relu, bf16-split out)
    gather256_kernel<false, false, 1><<<GATHER_GRID, 256>>>(d_rowptr, d_esrc, d_enorm, d_x, d_dinv, nullptr, nullptr, d_th, d_tl);
    { dim3 g(4, MT); hmma_gemm_kernel<128, 2><<<g, 256, HMMA_SMEM_128>>>(d_th, d_tl, w3h, w3l, b[2], nullptr, d_xh, d_xl, NN, 256, 512); }

    // L4 (post-agg, 512->256): hmma (fp32 out) -> gather (bias+relu, split out)
    { dim3 g(2, MT); hmma_gemm_kernel<128, 0><<<g, 256, HMMA_SMEM_128>>>(d_xh, d_xl, w4h, w4l, nullptr, d_t, nullptr, nullptr, NN, 512, 256); }
    gather256_kernel<true, true, 1><<<GATHER_GRID, 256>>>(d_rowptr, d_esrc, d_enorm, d_t, d_dinv, b[3], nullptr, d_th, d_tl);

    // L5 (post-agg, 256->64): hmma BN=64 (fp32 out) -> gather (bias+relu, fp32 out)
    { dim3 g(1, MT); hmma_gemm_kernel<64, 0><<<g, 256, HMMA_SMEM_64>>>(d_th, d_tl, w5h, w5l, nullptr, d_t, nullptr, nullptr, NN, 256, 64); }
    gather64_kernel<true, true, 0><<<GATHER_GRID, 256>>>(d_rowptr, d_esrc, d_enorm, d_t, d_dinv, b[4], d_x, nullptr, nullptr);

    // L6 (post-agg, 64->16, fp32, no relu) -> d_out
    { dim3 g(1, MT); sgemm_kernel<64, false><<<g, 128>>>(d_x, W[5], nullptr, d_t, NN, 64, 16); }
    gather_kernel<16, true, false><<<GATHER_GRID, 256>>>(d_rowptr, d_esrc, d_enorm, d_t, d_dinv, b[5], (float*)d_out);
}